// round 11
// baseline (speedup 1.0000x reference)
#include <cuda_runtime.h>
#include <cuda_bf16.h>
#include <cstdint>

// ---------------------------------------------------------------------------
// SwinBlock: B=32, H=W=56, C=192, heads=6, head_dim=32, WS=7, SS=3, N=49
// bf16 mma.sync GEMMs + register flash attention w/ precomputed bias table.
// ---------------------------------------------------------------------------

#define HW      56
#define Cdim    192
#define NHEADS  6
#define HDIM    32
#define WSZ     7
#define SSH     3
#define NTOK    49
#define NWIN    2048
#define MROWS   100352
#define HID     768
#define SCALE   0.17677669529663687f
#define SROW    72      // bf16 elems per smem row (64 data + 8 pad)

typedef __nv_bfloat16 bf16;
typedef __nv_bfloat162 bf162;

// -------------------------- scratch (device globals) -----------------------
__device__ __align__(16) bf16  g_winb [(size_t)MROWS * Cdim];
__device__ __align__(16) bf16  g_qkvb [(size_t)MROWS * 3 * Cdim];
__device__ __align__(16) bf16  g_attnob[(size_t)MROWS * Cdim];
__device__ __align__(16) float g_h    [(size_t)MROWS * Cdim];
__device__ __align__(16) bf16  g_ln2b [(size_t)MROWS * Cdim];
__device__ __align__(16) bf16  g_hidb [(size_t)MROWS * HID];
__device__ __align__(16) bf16  g_qkvwT[576 * 192];
__device__ __align__(16) bf16  g_projwT[192 * 192];
__device__ __align__(16) bf16  g_w1T  [HID * 192];
__device__ __align__(16) bf16  g_w2T  [192 * HID];
__device__ __align__(16) float g_bias [24 * 64 * 64];   // [cls*6+head][r][c]

// ------------------------------ helpers ------------------------------------
__device__ __forceinline__ void cpasync16(bf16* dst, const bf16* src) {
    uint32_t d = (uint32_t)__cvta_generic_to_shared(dst);
    asm volatile("cp.async.cg.shared.global [%0], [%1], 16;" :: "r"(d), "l"(src));
}
#define CP_COMMIT() asm volatile("cp.async.commit_group;" ::: "memory")

__device__ __forceinline__ void mma_bf16(float* d, const uint32_t* a, const uint32_t* b) {
    asm volatile(
        "mma.sync.aligned.m16n8k16.row.col.f32.bf16.bf16.f32 "
        "{%0,%1,%2,%3}, {%4,%5,%6,%7}, {%8,%9}, {%0,%1,%2,%3};"
        : "+f"(d[0]), "+f"(d[1]), "+f"(d[2]), "+f"(d[3])
        : "r"(a[0]), "r"(a[1]), "r"(a[2]), "r"(a[3]), "r"(b[0]), "r"(b[1]));
}

__device__ __forceinline__ void ldsm_x4(uint32_t* r, uint32_t addr) {
    asm volatile("ldmatrix.sync.aligned.m8n8.x4.shared.b16 {%0,%1,%2,%3}, [%4];"
        : "=r"(r[0]), "=r"(r[1]), "=r"(r[2]), "=r"(r[3]) : "r"(addr));
}
__device__ __forceinline__ void ldsm_x2(uint32_t* r, uint32_t addr) {
    asm volatile("ldmatrix.sync.aligned.m8n8.x2.shared.b16 {%0,%1}, [%2];"
        : "=r"(r[0]), "=r"(r[1]) : "r"(addr));
}

__device__ __forceinline__ uint32_t pack_bf162(float lo, float hi) {
    bf162 t = __floats2bfloat162_rn(lo, hi);
    return *(uint32_t*)&t;
}

__device__ __forceinline__ int permrow(int rw) {
    int win = rw / NTOK, n = rw - win * NTOK;
    int b   = win >> 6, wi = win & 63;
    int wh  = wi >> 3,  ww = wi & 7;
    int i   = n / WSZ,  j  = n - i * WSZ;
    int hs  = wh * WSZ + i + SSH; if (hs >= HW) hs -= HW;
    int ws  = ww * WSZ + j + SSH; if (ws >= HW) ws -= HW;
    return b * (HW * HW) + hs * HW + ws;
}

// ------------------ combined rpb + shift-mask bias table -------------------
// 4 window classes x 6 heads; [64][64] fp32; pad rows/cols = -1e30
__global__ void build_bias(const float* __restrict__ rpb_table, float* __restrict__ bias) {
    int idx = blockIdx.x;
    int cls = idx / NHEADS, head = idx - cls * NHEADS;
    int whE = cls >> 1, wwE = cls & 1;
    for (int e = threadIdx.x; e < 4096; e += 256) {
        int r = e >> 6, c = e & 63;
        float v = -1e30f;
        if (r < NTOK && c < NTOK) {
            int ri = r / 7, ci = r - ri * 7;
            int rj = c / 7, cj = c - rj * 7;
            v = rpb_table[((ri - rj + 6) * 13 + (ci - cj + 6)) * NHEADS + head];
            int gr = (whE ? (ri < 4 ? 1 : 2) : 0) * 3 + (wwE ? (ci < 4 ? 1 : 2) : 0);
            int gc = (whE ? (rj < 4 ? 1 : 2) : 0) * 3 + (wwE ? (cj < 4 ? 1 : 2) : 0);
            if (gr != gc) v -= 100.f;
        }
        bias[(size_t)idx * 4096 + e] = v;
    }
}

// ------------------ merged weight transpose (fp32 -> bf16 T) ----------------
__global__ void transpose_all(const float* __restrict__ qkvw,
                              const float* __restrict__ projw,
                              const float* __restrict__ w1,
                              const float* __restrict__ w2,
                              bf16* __restrict__ o0, bf16* __restrict__ o1,
                              bf16* __restrict__ o2, bf16* __restrict__ o3) {
    __shared__ float t[32][33];
    const float* in; bf16* out; int R, C;
    switch (blockIdx.z) {
        case 0: in = qkvw;  out = o0; R = 192; C = 576; break;
        case 1: in = projw; out = o1; R = 192; C = 192; break;
        case 2: in = w1;    out = o2; R = 192; C = 768; break;
        default:in = w2;    out = o3; R = 768; C = 192; break;
    }
    int bx = blockIdx.x * 32, by = blockIdx.y * 32;
    if (bx >= C || by >= R) return;
    int x = threadIdx.x, y0 = threadIdx.y;
    #pragma unroll
    for (int j = 0; j < 32; j += 8)
        t[y0 + j][x] = in[(size_t)(by + y0 + j) * C + bx + x];
    __syncthreads();
    #pragma unroll
    for (int j = 0; j < 32; j += 8)
        out[(size_t)(bx + y0 + j) * R + by + x] = __float2bfloat16_rn(t[x][y0 + j]);
}

// ------------------------- LN1 (warp/row, permuted read) -------------------
__global__ __launch_bounds__(256)
void ln_kernel(const float* __restrict__ in, const float* __restrict__ gamma,
               const float* __restrict__ beta, bf16* __restrict__ out) {
    int wid = threadIdx.x >> 5, lane = threadIdx.x & 31;
    int row = blockIdx.x * 8 + wid;
    int src = permrow(row);
    const float* p = in + (size_t)src * Cdim;

    float v[6];
    #pragma unroll
    for (int j = 0; j < 3; j++) {
        float2 xv = *(const float2*)&p[2 * lane + 64 * j];
        v[2 * j] = xv.x; v[2 * j + 1] = xv.y;
    }
    float s = v[0] + v[1] + v[2] + v[3] + v[4] + v[5];
    #pragma unroll
    for (int o = 16; o; o >>= 1) s += __shfl_xor_sync(0xffffffffu, s, o);
    float mu = s * (1.0f / Cdim);
    float sq = 0.f;
    #pragma unroll
    for (int j = 0; j < 6; j++) { v[j] -= mu; sq += v[j] * v[j]; }
    #pragma unroll
    for (int o = 16; o; o >>= 1) sq += __shfl_xor_sync(0xffffffffu, sq, o);
    float inv = rsqrtf(sq * (1.0f / Cdim) + 1e-5f);

    bf16* q = out + (size_t)row * Cdim;
    #pragma unroll
    for (int j = 0; j < 3; j++) {
        int c = 2 * lane + 64 * j;
        float o0 = v[2 * j] * inv * gamma[c] + beta[c];
        float o1 = v[2 * j + 1] * inv * gamma[c + 1] + beta[c + 1];
        *(bf162*)(q + c) = __floats2bfloat162_rn(o0, o1);
    }
}

// --------------------------- bf16 mma.sync GEMM ----------------------------
template<int CTA_N>
__device__ __forceinline__ void gload(const bf16* __restrict__ A,
                                      const bf16* __restrict__ BT,
                                      bf16* As, bf16* Bs,
                                      int mBase, int nBase, int K, int k0, int tid) {
    #pragma unroll
    for (int i = 0; i < 4; i++) {
        int idx = tid + i * 256;
        int r = idx >> 3, ch = idx & 7;
        cpasync16(As + r * SROW + ch * 8, A + (size_t)(mBase + r) * K + k0 + ch * 8);
    }
    #pragma unroll
    for (int i = 0; i < CTA_N * 8; i += 256) {
        int idx = tid + i;
        int r = idx >> 3, ch = idx & 7;
        cpasync16(Bs + r * SROW + ch * 8, BT + (size_t)(nBase + r) * K + k0 + ch * 8);
    }
    CP_COMMIT();
}

template<int EPI, int NT, bool OBF16>
__global__ __launch_bounds__(256)
void tc_gemm(const bf16* __restrict__ A, const bf16* __restrict__ BT,
             const float* __restrict__ bias, void* __restrict__ Cv,
             int N, int K, const float* __restrict__ resid,
             bf16* __restrict__ C2, const float* __restrict__ g2,
             const float* __restrict__ b2v) {
    constexpr int CTA_N = NT * 32;
    extern __shared__ __align__(16) bf16 sm[];
    bf16* AsBase = sm;
    bf16* BsBase = sm + 2 * 128 * SROW;

    int tid  = threadIdx.x;
    int wid  = tid >> 5, lane = tid & 31;
    int g    = lane >> 2, tig = lane & 3;
    int wm   = wid & 1, wn = wid >> 1;
    int mBase = blockIdx.x * 128;
    int nBase = blockIdx.y * CTA_N;
    int nk = K >> 6;

    int aRow = wm * 64 + (lane & 15);
    int aCol = (lane >> 4) << 3;
    int bRow = wn * NT * 8 + (lane & 7);
    int bCol = ((lane >> 3) & 1) << 3;

    float acc[4][NT][4];
    #pragma unroll
    for (int mt = 0; mt < 4; mt++)
        #pragma unroll
        for (int nt = 0; nt < NT; nt++)
            #pragma unroll
            for (int e = 0; e < 4; e++) acc[mt][nt][e] = 0.f;

    gload<CTA_N>(A, BT, AsBase, BsBase, mBase, nBase, K, 0, tid);

    for (int kt = 0; kt < nk; kt++) {
        int buf = kt & 1;
        if (kt + 1 < nk) {
            gload<CTA_N>(A, BT, AsBase + (buf ^ 1) * 128 * SROW,
                         BsBase + (buf ^ 1) * CTA_N * SROW,
                         mBase, nBase, K, (kt + 1) << 6, tid);
            asm volatile("cp.async.wait_group 1;" ::: "memory");
        } else {
            asm volatile("cp.async.wait_group 0;" ::: "memory");
        }
        __syncthreads();

        const bf16* As = AsBase + buf * 128 * SROW;
        const bf16* Bs = BsBase + buf * CTA_N * SROW;
        uint32_t aq = (uint32_t)__cvta_generic_to_shared(As + aRow * SROW + aCol);
        uint32_t bq = (uint32_t)__cvta_generic_to_shared(Bs + bRow * SROW + bCol);

        #pragma unroll
        for (int s = 0; s < 4; s++) {
            uint32_t a[4][4], b[NT][2];
            #pragma unroll
            for (int mt = 0; mt < 4; mt++)
                ldsm_x4(a[mt], aq + (mt * 16 * SROW + s * 16) * 2);
            #pragma unroll
            for (int nt = 0; nt < NT; nt++)
                ldsm_x2(b[nt], bq + (nt * 8 * SROW + s * 16) * 2);
            #pragma unroll
            for (int mt = 0; mt < 4; mt++)
                #pragma unroll
                for (int nt = 0; nt < NT; nt++)
                    mma_bf16(acc[mt][nt], a[mt], b[nt]);
        }
        __syncthreads();
    }

    // ---------------- epilogue ----------------
    float* s_sum = (float*)(sm + 2 * (128 + CTA_N) * SROW);
    float* s_sq  = s_sum + 512;

    #pragma unroll
    for (int mt = 0; mt < 4; mt++) {
        int lr0 = wm * 64 + mt * 16 + g;
        int lr1 = lr0 + 8;
        int r0 = mBase + lr0, r1 = mBase + lr1;
        int p0 = r0, p1 = r1;
        if (EPI == 2) { p0 = permrow(r0); p1 = permrow(r1); }

        float s0 = 0.f, q0 = 0.f, s1 = 0.f, q1 = 0.f;
        #pragma unroll
        for (int nt = 0; nt < NT; nt++) {
            int c = nBase + wn * NT * 8 + nt * 8 + 2 * tig;
            float2 bv = *(const float2*)(bias + c);
            float v0 = acc[mt][nt][0] + bv.x;
            float v1 = acc[mt][nt][1] + bv.y;
            float v2 = acc[mt][nt][2] + bv.x;
            float v3 = acc[mt][nt][3] + bv.y;
            if (EPI == 1) {
                v0 = 0.5f * v0 * (1.0f + erff(v0 * 0.70710678118654752f));
                v1 = 0.5f * v1 * (1.0f + erff(v1 * 0.70710678118654752f));
                v2 = 0.5f * v2 * (1.0f + erff(v2 * 0.70710678118654752f));
                v3 = 0.5f * v3 * (1.0f + erff(v3 * 0.70710678118654752f));
            } else if (EPI == 2) {
                float2 ra = *(const float2*)(resid + (size_t)p0 * Cdim + c);
                float2 rb = *(const float2*)(resid + (size_t)p1 * Cdim + c);
                v0 += ra.x; v1 += ra.y; v2 += rb.x; v3 += rb.y;
                s0 += v0 + v1; q0 += v0 * v0 + v1 * v1;
                s1 += v2 + v3; q1 += v2 * v2 + v3 * v3;
                acc[mt][nt][0] = v0; acc[mt][nt][1] = v1;
                acc[mt][nt][2] = v2; acc[mt][nt][3] = v3;
            } else if (EPI == 3) {
                float2 ra = *(const float2*)(resid + (size_t)r0 * Cdim + c);
                float2 rb = *(const float2*)(resid + (size_t)r1 * Cdim + c);
                v0 += ra.x; v1 += ra.y; v2 += rb.x; v3 += rb.y;
            }
            if (OBF16) {
                bf16* Cb = (bf16*)Cv;
                *(bf162*)(Cb + (size_t)p0 * N + c) = __floats2bfloat162_rn(v0, v1);
                *(bf162*)(Cb + (size_t)p1 * N + c) = __floats2bfloat162_rn(v2, v3);
            } else {
                float* Cf = (float*)Cv;
                *(float2*)(Cf + (size_t)p0 * N + c) = make_float2(v0, v1);
                *(float2*)(Cf + (size_t)p1 * N + c) = make_float2(v2, v3);
            }
        }
        if (EPI == 2) {
            #pragma unroll
            for (int o = 1; o < 4; o <<= 1) {
                s0 += __shfl_xor_sync(0xffffffffu, s0, o);
                q0 += __shfl_xor_sync(0xffffffffu, q0, o);
                s1 += __shfl_xor_sync(0xffffffffu, s1, o);
                q1 += __shfl_xor_sync(0xffffffffu, q1, o);
            }
            if (tig == 0) {
                s_sum[wn * 128 + lr0] = s0;  s_sq[wn * 128 + lr0] = q0;
                s_sum[wn * 128 + lr1] = s1;  s_sq[wn * 128 + lr1] = q1;
            }
        }
    }

    if (EPI == 2) {
        __syncthreads();
        #pragma unroll
        for (int mt = 0; mt < 4; mt++) {
            int lr0 = wm * 64 + mt * 16 + g;
            int lr1 = lr0 + 8;
            int p0 = permrow(mBase + lr0), p1 = permrow(mBase + lr1);
            float su0 = s_sum[lr0] + s_sum[128 + lr0] + s_sum[256 + lr0] + s_sum[384 + lr0];
            float sq0 = s_sq[lr0]  + s_sq[128 + lr0]  + s_sq[256 + lr0]  + s_sq[384 + lr0];
            float su1 = s_sum[lr1] + s_sum[128 + lr1] + s_sum[256 + lr1] + s_sum[384 + lr1];
            float sq1 = s_sq[lr1]  + s_sq[128 + lr1]  + s_sq[256 + lr1]  + s_sq[384 + lr1];
            float mu0 = su0 * (1.0f / Cdim);
            float mu1 = su1 * (1.0f / Cdim);
            float iv0 = rsqrtf(sq0 * (1.0f / Cdim) - mu0 * mu0 + 1e-5f);
            float iv1 = rsqrtf(sq1 * (1.0f / Cdim) - mu1 * mu1 + 1e-5f);
            #pragma unroll
            for (int nt = 0; nt < NT; nt++) {
                int c = wn * NT * 8 + nt * 8 + 2 * tig;
                float2 gv = *(const float2*)(g2 + c);
                float2 bb = *(const float2*)(b2v + c);
                float o0 = (acc[mt][nt][0] - mu0) * iv0 * gv.x + bb.x;
                float o1 = (acc[mt][nt][1] - mu0) * iv0 * gv.y + bb.y;
                float o2 = (acc[mt][nt][2] - mu1) * iv1 * gv.x + bb.x;
                float o3 = (acc[mt][nt][3] - mu1) * iv1 * gv.y + bb.y;
                *(bf162*)(C2 + (size_t)p0 * Cdim + c) = __floats2bfloat162_rn(o0, o1);
                *(bf162*)(C2 + (size_t)p1 * Cdim + c) = __floats2bfloat162_rn(o2, o3);
            }
        }
    }
}

// ------------------- register-resident flash attention ---------------------
// grid (NWIN, 3): one block per (window, head-pair); 8 warps = 2 heads x 4 rows.
// ldmatrix fragments + precomputed bias table (no mask ALU in hot loop).
__global__ __launch_bounds__(256)
void attn_kernel(const float* __restrict__ biasTab) {
    __shared__ __align__(16) bf16 Qs[2][64][40];
    __shared__ __align__(16) bf16 Ks[2][64][40];
    __shared__ __align__(16) bf16 Vt[2][32][72];   // [head][d][token]

    int win = blockIdx.x;
    int h0  = blockIdx.y * 2;
    int tid = threadIdx.x;
    int wid = tid >> 5, lane = tid & 31;
    int g = lane >> 2, tig = lane & 3;
    int hsel = wid >> 2, wm2 = wid & 3;
    int wi = win & 63;
    int wh = wi >> 3, ww = wi & 7;
    int cls = ((wh == 7) ? 2 : 0) + ((ww == 7) ? 1 : 0);

    // zero K pad rows (49..63) and V pad tokens (49..63)
    for (int idx = tid; idx < 2 * 15 * 20; idx += 256) {
        int hh = idx / 300, rem = idx - hh * 300;
        int rr = 49 + rem / 20, e = rem % 20;
        *(uint32_t*)&Ks[hh][rr][e * 2] = 0u;
    }
    for (int idx = tid; idx < 2 * 32 * 15; idx += 256) {
        int hh = idx / 480, rem = idx - hh * 480;
        int d = rem / 15, n = 49 + rem % 15;
        Vt[hh][d][n] = __float2bfloat16(0.f);
    }

    const bf16* base = g_qkvb + (size_t)win * NTOK * 576;

    // Q, K: 49 tokens x (2 heads x 2 mats x 4 chunks)
    for (int idx = tid; idx < 784; idx += 256) {
        int n = idx >> 4, sub = idx & 15;
        int hh = sub >> 3, mat = (sub >> 2) & 1, ch = sub & 3;
        uint4 v = *(const uint4*)(base + (size_t)n * 576 + mat * 192 + (h0 + hh) * 32 + ch * 8);
        *(uint4*)(&(mat ? Ks : Qs)[hh][n][ch * 8]) = v;
    }
    // V transposed
    for (int idx = tid; idx < 392; idx += 256) {
        int n = idx >> 3, hh = (idx >> 2) & 1, ch = idx & 3;
        uint4 v = *(const uint4*)(base + (size_t)n * 576 + 384 + (h0 + hh) * 32 + ch * 8);
        bf16 tmp[8]; *(uint4*)tmp = v;
        #pragma unroll
        for (int e = 0; e < 8; e++) Vt[hh][ch * 8 + e][n] = tmp[e];
    }
    __syncthreads();

    int r0 = wm2 * 16 + g, r1 = r0 + 8;
    float sf[8][4];
    #pragma unroll
    for (int j = 0; j < 8; j++)
        #pragma unroll
        for (int e = 0; e < 4; e++) sf[j][e] = 0.f;

    // ---- S = Q K^T via ldmatrix fragments ----
    uint32_t q_addr = (uint32_t)__cvta_generic_to_shared(
        &Qs[hsel][wm2 * 16 + (lane & 15)][(lane >> 4) * 8]);
    uint32_t k_addr = (uint32_t)__cvta_generic_to_shared(
        &Ks[hsel][(lane & 7) + ((lane >> 3) & 1) * 8][(lane >> 4) * 8]);

    #pragma unroll
    for (int s = 0; s < 2; s++) {
        uint32_t a[4];
        ldsm_x4(a, q_addr + s * 32);
        #pragma unroll
        for (int jp = 0; jp < 4; jp++) {
            uint32_t bb[4];
            ldsm_x4(bb, k_addr + (jp * 16 * 40 + s * 16) * 2);
            uint32_t bA[2] = {bb[0], bb[2]};
            uint32_t bB[2] = {bb[1], bb[3]};
            mma_bf16(sf[2 * jp],     a, bA);
            mma_bf16(sf[2 * jp + 1], a, bB);
        }
    }

    // ---- scale + precomputed bias (rpb + shift-mask + pad -1e30) ----
    const float* bp = biasTab + (size_t)(cls * NHEADS + h0 + hsel) * 4096;
    #pragma unroll
    for (int j = 0; j < 8; j++) {
        int c0 = j * 8 + 2 * tig;
        float2 ba = *(const float2*)(bp + r0 * 64 + c0);
        float2 bc = *(const float2*)(bp + r1 * 64 + c0);
        sf[j][0] = sf[j][0] * SCALE + ba.x;
        sf[j][1] = sf[j][1] * SCALE + ba.y;
        sf[j][2] = sf[j][2] * SCALE + bc.x;
        sf[j][3] = sf[j][3] * SCALE + bc.y;
    }

    // ---- softmax in registers (reduce across quad: shfl 1,2) ----
    float m0 = -1e30f, m1 = -1e30f;
    #pragma unroll
    for (int j = 0; j < 8; j++) {
        m0 = fmaxf(m0, fmaxf(sf[j][0], sf[j][1]));
        m1 = fmaxf(m1, fmaxf(sf[j][2], sf[j][3]));
    }
    m0 = fmaxf(m0, __shfl_xor_sync(0xffffffffu, m0, 1));
    m0 = fmaxf(m0, __shfl_xor_sync(0xffffffffu, m0, 2));
    m1 = fmaxf(m1, __shfl_xor_sync(0xffffffffu, m1, 1));
    m1 = fmaxf(m1, __shfl_xor_sync(0xffffffffu, m1, 2));
    float s0 = 0.f, s1 = 0.f;
    #pragma unroll
    for (int j = 0; j < 8; j++) {
        sf[j][0] = __expf(sf[j][0] - m0); s0 += sf[j][0];
        sf[j][1] = __expf(sf[j][1] - m0); s0 += sf[j][1];
        sf[j][2] = __expf(sf[j][2] - m1); s1 += sf[j][2];
        sf[j][3] = __expf(sf[j][3] - m1); s1 += sf[j][3];
    }
    s0 += __shfl_xor_sync(0xffffffffu, s0, 1);
    s0 += __shfl_xor_sync(0xffffffffu, s0, 2);
    s1 += __shfl_xor_sync(0xffffffffu, s1, 1);
    s1 += __shfl_xor_sync(0xffffffffu, s1, 2);
    float inv0 = __fdividef(1.0f, s0);
    float inv1 = __fdividef(1.0f, s1);

    // ---- pack P into A fragments directly from accumulators ----
    uint32_t pa[4][4];
    #pragma unroll
    for (int ks = 0; ks < 4; ks++) {
        pa[ks][0] = pack_bf162(sf[2 * ks][0] * inv0, sf[2 * ks][1] * inv0);
        pa[ks][1] = pack_bf162(sf[2 * ks][2] * inv1, sf[2 * ks][3] * inv1);
        pa[ks][2] = pack_bf162(sf[2 * ks + 1][0] * inv0, sf[2 * ks + 1][1] * inv0);
        pa[ks][3] = pack_bf162(sf[2 * ks + 1][2] * inv1, sf[2 * ks + 1][3] * inv1);
    }

    // ---- O = P V via ldmatrix fragments ----
    uint32_t v_addr = (uint32_t)__cvta_generic_to_shared(
        &Vt[hsel][(lane & 7) + ((lane >> 3) & 1) * 8][(lane >> 4) * 8]);
    float of[4][4];
    #pragma unroll
    for (int t = 0; t < 4; t++)
        #pragma unroll
        for (int e = 0; e < 4; e++) of[t][e] = 0.f;
    #pragma unroll
    for (int ks = 0; ks < 4; ks++) {
        #pragma unroll
        for (int tp = 0; tp < 2; tp++) {
            uint32_t bb[4];
            ldsm_x4(bb, v_addr + (tp * 16 * 72 + ks * 16) * 2);
            uint32_t bA[2] = {bb[0], bb[2]};
            uint32_t bB[2] = {bb[1], bb[3]};
            mma_bf16(of[2 * tp],     pa[ks], bA);
            mma_bf16(of[2 * tp + 1], pa[ks], bB);
        }
    }

    // ---- store O ----
    int h = h0 + hsel;
    #pragma unroll
    for (int t = 0; t < 4; t++) {
        int c = t * 8 + 2 * tig;
        if (r0 < 49) {
            bf16* o = g_attnob + (size_t)(win * NTOK + r0) * Cdim + h * HDIM + c;
            *(bf162*)o = __floats2bfloat162_rn(of[t][0], of[t][1]);
        }
        if (r1 < 49) {
            bf16* o = g_attnob + (size_t)(win * NTOK + r1) * Cdim + h * HDIM + c;
            *(bf162*)o = __floats2bfloat162_rn(of[t][2], of[t][3]);
        }
    }
}

// ------------------------------ launcher -----------------------------------
#define SM3 (2 * (128 + 96) * SROW * 2)                    // 64512 B
#define SM6 (2 * (128 + 192) * SROW * 2 + 4096)            // 96256 B

extern "C" void kernel_launch(void* const* d_in, const int* in_sizes, int n_in,
                              void* d_out, int out_size) {
    const float* x      = (const float*)d_in[0];
    const float* qkv_w  = (const float*)d_in[1];
    const float* qkv_b  = (const float*)d_in[2];
    const float* proj_w = (const float*)d_in[3];
    const float* proj_b = (const float*)d_in[4];
    const float* rpb    = (const float*)d_in[5];
    const float* ln1_g  = (const float*)d_in[6];
    const float* ln1_b  = (const float*)d_in[7];
    const float* ln2_g  = (const float*)d_in[8];
    const float* ln2_b  = (const float*)d_in[9];
    const float* w1     = (const float*)d_in[10];
    const float* b1     = (const float*)d_in[11];
    const float* w2     = (const float*)d_in[12];
    const float* b2     = (const float*)d_in[13];
    float* out = (float*)d_out;

    bf16 *p_win, *p_qkv, *p_attno, *p_ln2, *p_hid;
    bf16 *p_qkvwT, *p_projwT, *p_w1T, *p_w2T;
    float *p_h, *p_bias;
    cudaGetSymbolAddress((void**)&p_win,    g_winb);
    cudaGetSymbolAddress((void**)&p_qkv,    g_qkvb);
    cudaGetSymbolAddress((void**)&p_attno,  g_attnob);
    cudaGetSymbolAddress((void**)&p_h,      g_h);
    cudaGetSymbolAddress((void**)&p_ln2,    g_ln2b);
    cudaGetSymbolAddress((void**)&p_hid,    g_hidb);
    cudaGetSymbolAddress((void**)&p_qkvwT,  g_qkvwT);
    cudaGetSymbolAddress((void**)&p_projwT, g_projwT);
    cudaGetSymbolAddress((void**)&p_w1T,    g_w1T);
    cudaGetSymbolAddress((void**)&p_w2T,    g_w2T);
    cudaGetSymbolAddress((void**)&p_bias,   g_bias);

    cudaFuncSetAttribute(tc_gemm<0,3,true>,  cudaFuncAttributeMaxDynamicSharedMemorySize, SM3);
    cudaFuncSetAttribute(tc_gemm<1,3,true>,  cudaFuncAttributeMaxDynamicSharedMemorySize, SM3);
    cudaFuncSetAttribute(tc_gemm<2,6,false>, cudaFuncAttributeMaxDynamicSharedMemorySize, SM6);
    cudaFuncSetAttribute(tc_gemm<3,3,false>, cudaFuncAttributeMaxDynamicSharedMemorySize, SM3);

    // 0. weight transposes + bias table
    transpose_all<<<dim3(24, 24, 4), dim3(32, 8)>>>(qkv_w, proj_w, w1, w2,
                                                    p_qkvwT, p_projwT, p_w1T, p_w2T);
    build_bias<<<24, 256>>>(rpb, p_bias);

    // 1. LN1 + shifted-window partition -> bf16
    ln_kernel<<<MROWS / 8, 256>>>(x, ln1_g, ln1_b, p_win);

    // 2. QKV: (100352,192) @ (192,576) -> bf16
    tc_gemm<0,3,true><<<dim3(MROWS / 128, 6), 256, SM3>>>(
        p_win, p_qkvwT, qkv_b, p_qkv, 576, 192, nullptr, nullptr, nullptr, nullptr);

    // 3. windowed attention (register flash; grid = window x head-pair)
    attn_kernel<<<dim3(NWIN, 3), 256>>>(p_bias);

    // 4. proj + window-reverse + residual(x) + fused LN2 (g_h fp32, g_ln2 bf16)
    tc_gemm<2,6,false><<<dim3(MROWS / 128, 1), 256, SM6>>>(
        p_attno, p_projwT, proj_b, p_h, 192, 192, x, p_ln2, ln2_g, ln2_b);

    // 5. MLP1 + GELU -> bf16
    tc_gemm<1,3,true><<<dim3(MROWS / 128, 8), 256, SM3>>>(
        p_ln2, p_w1T, b1, p_hid, HID, 192, nullptr, nullptr, nullptr, nullptr);

    // 6. MLP2 + residual(h) -> fp32 out
    tc_gemm<3,3,false><<<dim3(MROWS / 128, 2), 256, SM3>>>(
        p_hid, p_w2T, b2, out, 192, HID, p_h, nullptr, nullptr, nullptr);
}

// round 12
// speedup vs baseline: 1.0271x; 1.0271x over previous
#include <cuda_runtime.h>
#include <cuda_bf16.h>
#include <cstdint>

// ---------------------------------------------------------------------------
// SwinBlock: B=32, H=W=56, C=192, heads=6, head_dim=32, WS=7, SS=3, N=49
// bf16 mma.sync GEMMs (3 CTA/SM) + register flash attention w/ bias table.
// ---------------------------------------------------------------------------

#define HW      56
#define Cdim    192
#define NHEADS  6
#define HDIM    32
#define WSZ     7
#define SSH     3
#define NTOK    49
#define NWIN    2048
#define MROWS   100352
#define HID     768
#define SCALE   0.17677669529663687f
#define SROW    72      // bf16 elems per smem row (64 data + 8 pad)

typedef __nv_bfloat16 bf16;
typedef __nv_bfloat162 bf162;

// -------------------------- scratch (device globals) -----------------------
__device__ __align__(16) bf16  g_winb [(size_t)MROWS * Cdim];
__device__ __align__(16) bf16  g_qkvb [(size_t)MROWS * 3 * Cdim];
__device__ __align__(16) bf16  g_attnob[(size_t)MROWS * Cdim];
__device__ __align__(16) float g_h    [(size_t)MROWS * Cdim];
__device__ __align__(16) bf16  g_ln2b [(size_t)MROWS * Cdim];
__device__ __align__(16) bf16  g_hidb [(size_t)MROWS * HID];
__device__ __align__(16) bf16  g_qkvwT[576 * 192];
__device__ __align__(16) bf16  g_projwT[192 * 192];
__device__ __align__(16) bf16  g_w1T  [HID * 192];
__device__ __align__(16) bf16  g_w2T  [192 * HID];
__device__ __align__(16) float g_bias [24 * 64 * 64];   // [cls*6+head][r][c]

// ------------------------------ helpers ------------------------------------
__device__ __forceinline__ void cpasync16(bf16* dst, const bf16* src) {
    uint32_t d = (uint32_t)__cvta_generic_to_shared(dst);
    asm volatile("cp.async.cg.shared.global [%0], [%1], 16;" :: "r"(d), "l"(src));
}
#define CP_COMMIT() asm volatile("cp.async.commit_group;" ::: "memory")

__device__ __forceinline__ void mma_bf16(float* d, const uint32_t* a, const uint32_t* b) {
    asm volatile(
        "mma.sync.aligned.m16n8k16.row.col.f32.bf16.bf16.f32 "
        "{%0,%1,%2,%3}, {%4,%5,%6,%7}, {%8,%9}, {%0,%1,%2,%3};"
        : "+f"(d[0]), "+f"(d[1]), "+f"(d[2]), "+f"(d[3])
        : "r"(a[0]), "r"(a[1]), "r"(a[2]), "r"(a[3]), "r"(b[0]), "r"(b[1]));
}

__device__ __forceinline__ void ldsm_x4(uint32_t* r, uint32_t addr) {
    asm volatile("ldmatrix.sync.aligned.m8n8.x4.shared.b16 {%0,%1,%2,%3}, [%4];"
        : "=r"(r[0]), "=r"(r[1]), "=r"(r[2]), "=r"(r[3]) : "r"(addr));
}
__device__ __forceinline__ void ldsm_x2(uint32_t* r, uint32_t addr) {
    asm volatile("ldmatrix.sync.aligned.m8n8.x2.shared.b16 {%0,%1}, [%2];"
        : "=r"(r[0]), "=r"(r[1]) : "r"(addr));
}

__device__ __forceinline__ uint32_t pack_bf162(float lo, float hi) {
    bf162 t = __floats2bfloat162_rn(lo, hi);
    return *(uint32_t*)&t;
}

__device__ __forceinline__ int permrow(int rw) {
    int win = rw / NTOK, n = rw - win * NTOK;
    int b   = win >> 6, wi = win & 63;
    int wh  = wi >> 3,  ww = wi & 7;
    int i   = n / WSZ,  j  = n - i * WSZ;
    int hs  = wh * WSZ + i + SSH; if (hs >= HW) hs -= HW;
    int ws  = ww * WSZ + j + SSH; if (ws >= HW) ws -= HW;
    return b * (HW * HW) + hs * HW + ws;
}

// ------------------ combined rpb + shift-mask bias table -------------------
__global__ void build_bias(const float* __restrict__ rpb_table, float* __restrict__ bias) {
    int idx = blockIdx.x;
    int cls = idx / NHEADS, head = idx - cls * NHEADS;
    int whE = cls >> 1, wwE = cls & 1;
    for (int e = threadIdx.x; e < 4096; e += 256) {
        int r = e >> 6, c = e & 63;
        float v = -1e30f;
        if (r < NTOK && c < NTOK) {
            int ri = r / 7, ci = r - ri * 7;
            int rj = c / 7, cj = c - rj * 7;
            v = rpb_table[((ri - rj + 6) * 13 + (ci - cj + 6)) * NHEADS + head];
            int gr = (whE ? (ri < 4 ? 1 : 2) : 0) * 3 + (wwE ? (ci < 4 ? 1 : 2) : 0);
            int gc = (whE ? (rj < 4 ? 1 : 2) : 0) * 3 + (wwE ? (cj < 4 ? 1 : 2) : 0);
            if (gr != gc) v -= 100.f;
        }
        bias[(size_t)idx * 4096 + e] = v;
    }
}

// ------------------ merged weight transpose (fp32 -> bf16 T) ----------------
__global__ void transpose_all(const float* __restrict__ qkvw,
                              const float* __restrict__ projw,
                              const float* __restrict__ w1,
                              const float* __restrict__ w2,
                              bf16* __restrict__ o0, bf16* __restrict__ o1,
                              bf16* __restrict__ o2, bf16* __restrict__ o3) {
    __shared__ float t[32][33];
    const float* in; bf16* out; int R, C;
    switch (blockIdx.z) {
        case 0: in = qkvw;  out = o0; R = 192; C = 576; break;
        case 1: in = projw; out = o1; R = 192; C = 192; break;
        case 2: in = w1;    out = o2; R = 192; C = 768; break;
        default:in = w2;    out = o3; R = 768; C = 192; break;
    }
    int bx = blockIdx.x * 32, by = blockIdx.y * 32;
    if (bx >= C || by >= R) return;
    int x = threadIdx.x, y0 = threadIdx.y;
    #pragma unroll
    for (int j = 0; j < 32; j += 8)
        t[y0 + j][x] = in[(size_t)(by + y0 + j) * C + bx + x];
    __syncthreads();
    #pragma unroll
    for (int j = 0; j < 32; j += 8)
        out[(size_t)(bx + y0 + j) * R + by + x] = __float2bfloat16_rn(t[x][y0 + j]);
}

// ------------------------- LN1 (warp/row, permuted read) -------------------
__global__ __launch_bounds__(256)
void ln_kernel(const float* __restrict__ in, const float* __restrict__ gamma,
               const float* __restrict__ beta, bf16* __restrict__ out) {
    int wid = threadIdx.x >> 5, lane = threadIdx.x & 31;
    int row = blockIdx.x * 8 + wid;
    int src = permrow(row);
    const float* p = in + (size_t)src * Cdim;

    float v[6];
    #pragma unroll
    for (int j = 0; j < 3; j++) {
        float2 xv = *(const float2*)&p[2 * lane + 64 * j];
        v[2 * j] = xv.x; v[2 * j + 1] = xv.y;
    }
    float s = v[0] + v[1] + v[2] + v[3] + v[4] + v[5];
    #pragma unroll
    for (int o = 16; o; o >>= 1) s += __shfl_xor_sync(0xffffffffu, s, o);
    float mu = s * (1.0f / Cdim);
    float sq = 0.f;
    #pragma unroll
    for (int j = 0; j < 6; j++) { v[j] -= mu; sq += v[j] * v[j]; }
    #pragma unroll
    for (int o = 16; o; o >>= 1) sq += __shfl_xor_sync(0xffffffffu, sq, o);
    float inv = rsqrtf(sq * (1.0f / Cdim) + 1e-5f);

    bf16* q = out + (size_t)row * Cdim;
    #pragma unroll
    for (int j = 0; j < 3; j++) {
        int c = 2 * lane + 64 * j;
        float o0 = v[2 * j] * inv * gamma[c] + beta[c];
        float o1 = v[2 * j + 1] * inv * gamma[c + 1] + beta[c + 1];
        *(bf162*)(q + c) = __floats2bfloat162_rn(o0, o1);
    }
}

// --------------------------- bf16 mma.sync GEMM ----------------------------
template<int CTA_N>
__device__ __forceinline__ void gload(const bf16* __restrict__ A,
                                      const bf16* __restrict__ BT,
                                      bf16* As, bf16* Bs,
                                      int mBase, int nBase, int K, int k0, int tid) {
    #pragma unroll
    for (int i = 0; i < 4; i++) {
        int idx = tid + i * 256;
        int r = idx >> 3, ch = idx & 7;
        cpasync16(As + r * SROW + ch * 8, A + (size_t)(mBase + r) * K + k0 + ch * 8);
    }
    #pragma unroll
    for (int i = 0; i < CTA_N * 8; i += 256) {
        int idx = tid + i;
        int r = idx >> 3, ch = idx & 7;
        cpasync16(Bs + r * SROW + ch * 8, BT + (size_t)(nBase + r) * K + k0 + ch * 8);
    }
    CP_COMMIT();
}

template<int EPI, int NT, bool OBF16>
__global__ __launch_bounds__(256, (NT == 3) ? 3 : 1)
void tc_gemm(const bf16* __restrict__ A, const bf16* __restrict__ BT,
             const float* __restrict__ bias, void* __restrict__ Cv,
             int N, int K, const float* __restrict__ resid,
             bf16* __restrict__ C2, const float* __restrict__ g2,
             const float* __restrict__ b2v) {
    constexpr int CTA_N = NT * 32;
    extern __shared__ __align__(16) bf16 sm[];
    bf16* AsBase = sm;
    bf16* BsBase = sm + 2 * 128 * SROW;

    int tid  = threadIdx.x;
    int wid  = tid >> 5, lane = tid & 31;
    int g    = lane >> 2, tig = lane & 3;
    int wm   = wid & 1, wn = wid >> 1;
    int mBase = blockIdx.x * 128;
    int nBase = blockIdx.y * CTA_N;
    int nk = K >> 6;

    int aRow = wm * 64 + (lane & 15);
    int aCol = (lane >> 4) << 3;
    int bRow = wn * NT * 8 + (lane & 7);
    int bCol = ((lane >> 3) & 1) << 3;

    float acc[4][NT][4];
    #pragma unroll
    for (int mt = 0; mt < 4; mt++)
        #pragma unroll
        for (int nt = 0; nt < NT; nt++)
            #pragma unroll
            for (int e = 0; e < 4; e++) acc[mt][nt][e] = 0.f;

    gload<CTA_N>(A, BT, AsBase, BsBase, mBase, nBase, K, 0, tid);

    for (int kt = 0; kt < nk; kt++) {
        int buf = kt & 1;
        if (kt + 1 < nk) {
            gload<CTA_N>(A, BT, AsBase + (buf ^ 1) * 128 * SROW,
                         BsBase + (buf ^ 1) * CTA_N * SROW,
                         mBase, nBase, K, (kt + 1) << 6, tid);
            asm volatile("cp.async.wait_group 1;" ::: "memory");
        } else {
            asm volatile("cp.async.wait_group 0;" ::: "memory");
        }
        __syncthreads();

        const bf16* As = AsBase + buf * 128 * SROW;
        const bf16* Bs = BsBase + buf * CTA_N * SROW;
        uint32_t aq = (uint32_t)__cvta_generic_to_shared(As + aRow * SROW + aCol);
        uint32_t bq = (uint32_t)__cvta_generic_to_shared(Bs + bRow * SROW + bCol);

        #pragma unroll
        for (int s = 0; s < 4; s++) {
            uint32_t a[4][4], b[NT][2];
            #pragma unroll
            for (int mt = 0; mt < 4; mt++)
                ldsm_x4(a[mt], aq + (mt * 16 * SROW + s * 16) * 2);
            #pragma unroll
            for (int nt = 0; nt < NT; nt++)
                ldsm_x2(b[nt], bq + (nt * 8 * SROW + s * 16) * 2);
            #pragma unroll
            for (int mt = 0; mt < 4; mt++)
                #pragma unroll
                for (int nt = 0; nt < NT; nt++)
                    mma_bf16(acc[mt][nt], a[mt], b[nt]);
        }
        __syncthreads();
    }

    // ---------------- epilogue ----------------
    float* s_sum = (float*)(sm + 2 * (128 + CTA_N) * SROW);
    float* s_sq  = s_sum + 512;

    #pragma unroll
    for (int mt = 0; mt < 4; mt++) {
        int lr0 = wm * 64 + mt * 16 + g;
        int lr1 = lr0 + 8;
        int r0 = mBase + lr0, r1 = mBase + lr1;
        int p0 = r0, p1 = r1;
        if (EPI == 2) { p0 = permrow(r0); p1 = permrow(r1); }

        float s0 = 0.f, q0 = 0.f, s1 = 0.f, q1 = 0.f;
        #pragma unroll
        for (int nt = 0; nt < NT; nt++) {
            int c = nBase + wn * NT * 8 + nt * 8 + 2 * tig;
            float2 bv = *(const float2*)(bias + c);
            float v0 = acc[mt][nt][0] + bv.x;
            float v1 = acc[mt][nt][1] + bv.y;
            float v2 = acc[mt][nt][2] + bv.x;
            float v3 = acc[mt][nt][3] + bv.y;
            if (EPI == 1) {
                v0 = 0.5f * v0 * (1.0f + erff(v0 * 0.70710678118654752f));
                v1 = 0.5f * v1 * (1.0f + erff(v1 * 0.70710678118654752f));
                v2 = 0.5f * v2 * (1.0f + erff(v2 * 0.70710678118654752f));
                v3 = 0.5f * v3 * (1.0f + erff(v3 * 0.70710678118654752f));
            } else if (EPI == 2) {
                float2 ra = *(const float2*)(resid + (size_t)p0 * Cdim + c);
                float2 rb = *(const float2*)(resid + (size_t)p1 * Cdim + c);
                v0 += ra.x; v1 += ra.y; v2 += rb.x; v3 += rb.y;
                s0 += v0 + v1; q0 += v0 * v0 + v1 * v1;
                s1 += v2 + v3; q1 += v2 * v2 + v3 * v3;
                acc[mt][nt][0] = v0; acc[mt][nt][1] = v1;
                acc[mt][nt][2] = v2; acc[mt][nt][3] = v3;
            } else if (EPI == 3) {
                float2 ra = *(const float2*)(resid + (size_t)r0 * Cdim + c);
                float2 rb = *(const float2*)(resid + (size_t)r1 * Cdim + c);
                v0 += ra.x; v1 += ra.y; v2 += rb.x; v3 += rb.y;
            }
            if (OBF16) {
                bf16* Cb = (bf16*)Cv;
                *(bf162*)(Cb + (size_t)p0 * N + c) = __floats2bfloat162_rn(v0, v1);
                *(bf162*)(Cb + (size_t)p1 * N + c) = __floats2bfloat162_rn(v2, v3);
            } else {
                float* Cf = (float*)Cv;
                *(float2*)(Cf + (size_t)p0 * N + c) = make_float2(v0, v1);
                *(float2*)(Cf + (size_t)p1 * N + c) = make_float2(v2, v3);
            }
        }
        if (EPI == 2) {
            #pragma unroll
            for (int o = 1; o < 4; o <<= 1) {
                s0 += __shfl_xor_sync(0xffffffffu, s0, o);
                q0 += __shfl_xor_sync(0xffffffffu, q0, o);
                s1 += __shfl_xor_sync(0xffffffffu, s1, o);
                q1 += __shfl_xor_sync(0xffffffffu, q1, o);
            }
            if (tig == 0) {
                s_sum[wn * 128 + lr0] = s0;  s_sq[wn * 128 + lr0] = q0;
                s_sum[wn * 128 + lr1] = s1;  s_sq[wn * 128 + lr1] = q1;
            }
        }
    }

    if (EPI == 2) {
        __syncthreads();
        #pragma unroll
        for (int mt = 0; mt < 4; mt++) {
            int lr0 = wm * 64 + mt * 16 + g;
            int lr1 = lr0 + 8;
            int p0 = permrow(mBase + lr0), p1 = permrow(mBase + lr1);
            float su0 = s_sum[lr0] + s_sum[128 + lr0] + s_sum[256 + lr0] + s_sum[384 + lr0];
            float sq0 = s_sq[lr0]  + s_sq[128 + lr0]  + s_sq[256 + lr0]  + s_sq[384 + lr0];
            float su1 = s_sum[lr1] + s_sum[128 + lr1] + s_sum[256 + lr1] + s_sum[384 + lr1];
            float sq1 = s_sq[lr1]  + s_sq[128 + lr1]  + s_sq[256 + lr1]  + s_sq[384 + lr1];
            float mu0 = su0 * (1.0f / Cdim);
            float mu1 = su1 * (1.0f / Cdim);
            float iv0 = rsqrtf(sq0 * (1.0f / Cdim) - mu0 * mu0 + 1e-5f);
            float iv1 = rsqrtf(sq1 * (1.0f / Cdim) - mu1 * mu1 + 1e-5f);
            #pragma unroll
            for (int nt = 0; nt < NT; nt++) {
                int c = wn * NT * 8 + nt * 8 + 2 * tig;
                float2 gv = *(const float2*)(g2 + c);
                float2 bb = *(const float2*)(b2v + c);
                float o0 = (acc[mt][nt][0] - mu0) * iv0 * gv.x + bb.x;
                float o1 = (acc[mt][nt][1] - mu0) * iv0 * gv.y + bb.y;
                float o2 = (acc[mt][nt][2] - mu1) * iv1 * gv.x + bb.x;
                float o3 = (acc[mt][nt][3] - mu1) * iv1 * gv.y + bb.y;
                *(bf162*)(C2 + (size_t)p0 * Cdim + c) = __floats2bfloat162_rn(o0, o1);
                *(bf162*)(C2 + (size_t)p1 * Cdim + c) = __floats2bfloat162_rn(o2, o3);
            }
        }
    }
}

// ------------------- register-resident flash attention ---------------------
__global__ __launch_bounds__(256)
void attn_kernel(const float* __restrict__ biasTab) {
    __shared__ __align__(16) bf16 Qs[2][64][40];
    __shared__ __align__(16) bf16 Ks[2][64][40];
    __shared__ __align__(16) bf16 Vt[2][32][72];   // [head][d][token]

    int win = blockIdx.x;
    int h0  = blockIdx.y * 2;
    int tid = threadIdx.x;
    int wid = tid >> 5, lane = tid & 31;
    int g = lane >> 2, tig = lane & 3;
    int hsel = wid >> 2, wm2 = wid & 3;
    int wi = win & 63;
    int wh = wi >> 3, ww = wi & 7;
    int cls = ((wh == 7) ? 2 : 0) + ((ww == 7) ? 1 : 0);

    for (int idx = tid; idx < 2 * 15 * 20; idx += 256) {
        int hh = idx / 300, rem = idx - hh * 300;
        int rr = 49 + rem / 20, e = rem % 20;
        *(uint32_t*)&Ks[hh][rr][e * 2] = 0u;
    }
    for (int idx = tid; idx < 2 * 32 * 15; idx += 256) {
        int hh = idx / 480, rem = idx - hh * 480;
        int d = rem / 15, n = 49 + rem % 15;
        Vt[hh][d][n] = __float2bfloat16(0.f);
    }

    const bf16* base = g_qkvb + (size_t)win * NTOK * 576;

    for (int idx = tid; idx < 784; idx += 256) {
        int n = idx >> 4, sub = idx & 15;
        int hh = sub >> 3, mat = (sub >> 2) & 1, ch = sub & 3;
        uint4 v = *(const uint4*)(base + (size_t)n * 576 + mat * 192 + (h0 + hh) * 32 + ch * 8);
        *(uint4*)(&(mat ? Ks : Qs)[hh][n][ch * 8]) = v;
    }
    for (int idx = tid; idx < 392; idx += 256) {
        int n = idx >> 3, hh = (idx >> 2) & 1, ch = idx & 3;
        uint4 v = *(const uint4*)(base + (size_t)n * 576 + 384 + (h0 + hh) * 32 + ch * 8);
        bf16 tmp[8]; *(uint4*)tmp = v;
        #pragma unroll
        for (int e = 0; e < 8; e++) Vt[hh][ch * 8 + e][n] = tmp[e];
    }
    __syncthreads();

    int r0 = wm2 * 16 + g, r1 = r0 + 8;
    float sf[8][4];
    #pragma unroll
    for (int j = 0; j < 8; j++)
        #pragma unroll
        for (int e = 0; e < 4; e++) sf[j][e] = 0.f;

    uint32_t q_addr = (uint32_t)__cvta_generic_to_shared(
        &Qs[hsel][wm2 * 16 + (lane & 15)][(lane >> 4) * 8]);
    uint32_t k_addr = (uint32_t)__cvta_generic_to_shared(
        &Ks[hsel][(lane & 7) + ((lane >> 3) & 1) * 8][(lane >> 4) * 8]);

    #pragma unroll
    for (int s = 0; s < 2; s++) {
        uint32_t a[4];
        ldsm_x4(a, q_addr + s * 32);
        #pragma unroll
        for (int jp = 0; jp < 4; jp++) {
            uint32_t bb[4];
            ldsm_x4(bb, k_addr + (jp * 16 * 40 + s * 16) * 2);
            uint32_t bA[2] = {bb[0], bb[2]};
            uint32_t bB[2] = {bb[1], bb[3]};
            mma_bf16(sf[2 * jp],     a, bA);
            mma_bf16(sf[2 * jp + 1], a, bB);
        }
    }

    const float* bp = biasTab + (size_t)(cls * NHEADS + h0 + hsel) * 4096;
    #pragma unroll
    for (int j = 0; j < 8; j++) {
        int c0 = j * 8 + 2 * tig;
        float2 ba = *(const float2*)(bp + r0 * 64 + c0);
        float2 bc = *(const float2*)(bp + r1 * 64 + c0);
        sf[j][0] = sf[j][0] * SCALE + ba.x;
        sf[j][1] = sf[j][1] * SCALE + ba.y;
        sf[j][2] = sf[j][2] * SCALE + bc.x;
        sf[j][3] = sf[j][3] * SCALE + bc.y;
    }

    float m0 = -1e30f, m1 = -1e30f;
    #pragma unroll
    for (int j = 0; j < 8; j++) {
        m0 = fmaxf(m0, fmaxf(sf[j][0], sf[j][1]));
        m1 = fmaxf(m1, fmaxf(sf[j][2], sf[j][3]));
    }
    m0 = fmaxf(m0, __shfl_xor_sync(0xffffffffu, m0, 1));
    m0 = fmaxf(m0, __shfl_xor_sync(0xffffffffu, m0, 2));
    m1 = fmaxf(m1, __shfl_xor_sync(0xffffffffu, m1, 1));
    m1 = fmaxf(m1, __shfl_xor_sync(0xffffffffu, m1, 2));
    float s0 = 0.f, s1 = 0.f;
    #pragma unroll
    for (int j = 0; j < 8; j++) {
        sf[j][0] = __expf(sf[j][0] - m0); s0 += sf[j][0];
        sf[j][1] = __expf(sf[j][1] - m0); s0 += sf[j][1];
        sf[j][2] = __expf(sf[j][2] - m1); s1 += sf[j][2];
        sf[j][3] = __expf(sf[j][3] - m1); s1 += sf[j][3];
    }
    s0 += __shfl_xor_sync(0xffffffffu, s0, 1);
    s0 += __shfl_xor_sync(0xffffffffu, s0, 2);
    s1 += __shfl_xor_sync(0xffffffffu, s1, 1);
    s1 += __shfl_xor_sync(0xffffffffu, s1, 2);
    float inv0 = __fdividef(1.0f, s0);
    float inv1 = __fdividef(1.0f, s1);

    uint32_t pa[4][4];
    #pragma unroll
    for (int ks = 0; ks < 4; ks++) {
        pa[ks][0] = pack_bf162(sf[2 * ks][0] * inv0, sf[2 * ks][1] * inv0);
        pa[ks][1] = pack_bf162(sf[2 * ks][2] * inv1, sf[2 * ks][3] * inv1);
        pa[ks][2] = pack_bf162(sf[2 * ks + 1][0] * inv0, sf[2 * ks + 1][1] * inv0);
        pa[ks][3] = pack_bf162(sf[2 * ks + 1][2] * inv1, sf[2 * ks + 1][3] * inv1);
    }

    uint32_t v_addr = (uint32_t)__cvta_generic_to_shared(
        &Vt[hsel][(lane & 7) + ((lane >> 3) & 1) * 8][(lane >> 4) * 8]);
    float of[4][4];
    #pragma unroll
    for (int t = 0; t < 4; t++)
        #pragma unroll
        for (int e = 0; e < 4; e++) of[t][e] = 0.f;
    #pragma unroll
    for (int ks = 0; ks < 4; ks++) {
        #pragma unroll
        for (int tp = 0; tp < 2; tp++) {
            uint32_t bb[4];
            ldsm_x4(bb, v_addr + (tp * 16 * 72 + ks * 16) * 2);
            uint32_t bA[2] = {bb[0], bb[2]};
            uint32_t bB[2] = {bb[1], bb[3]};
            mma_bf16(of[2 * tp],     pa[ks], bA);
            mma_bf16(of[2 * tp + 1], pa[ks], bB);
        }
    }

    int h = h0 + hsel;
    #pragma unroll
    for (int t = 0; t < 4; t++) {
        int c = t * 8 + 2 * tig;
        if (r0 < 49) {
            bf16* o = g_attnob + (size_t)(win * NTOK + r0) * Cdim + h * HDIM + c;
            *(bf162*)o = __floats2bfloat162_rn(of[t][0], of[t][1]);
        }
        if (r1 < 49) {
            bf16* o = g_attnob + (size_t)(win * NTOK + r1) * Cdim + h * HDIM + c;
            *(bf162*)o = __floats2bfloat162_rn(of[t][2], of[t][3]);
        }
    }
}

// ------------------------------ launcher -----------------------------------
#define SM3 (2 * (128 + 96) * SROW * 2)                    // 64512 B
#define SM6 (2 * (128 + 192) * SROW * 2 + 4096)            // 96256 B

extern "C" void kernel_launch(void* const* d_in, const int* in_sizes, int n_in,
                              void* d_out, int out_size) {
    const float* x      = (const float*)d_in[0];
    const float* qkv_w  = (const float*)d_in[1];
    const float* qkv_b  = (const float*)d_in[2];
    const float* proj_w = (const float*)d_in[3];
    const float* proj_b = (const float*)d_in[4];
    const float* rpb    = (const float*)d_in[5];
    const float* ln1_g  = (const float*)d_in[6];
    const float* ln1_b  = (const float*)d_in[7];
    const float* ln2_g  = (const float*)d_in[8];
    const float* ln2_b  = (const float*)d_in[9];
    const float* w1     = (const float*)d_in[10];
    const float* b1     = (const float*)d_in[11];
    const float* w2     = (const float*)d_in[12];
    const float* b2     = (const float*)d_in[13];
    float* out = (float*)d_out;

    bf16 *p_win, *p_qkv, *p_attno, *p_ln2, *p_hid;
    bf16 *p_qkvwT, *p_projwT, *p_w1T, *p_w2T;
    float *p_h, *p_bias;
    cudaGetSymbolAddress((void**)&p_win,    g_winb);
    cudaGetSymbolAddress((void**)&p_qkv,    g_qkvb);
    cudaGetSymbolAddress((void**)&p_attno,  g_attnob);
    cudaGetSymbolAddress((void**)&p_h,      g_h);
    cudaGetSymbolAddress((void**)&p_ln2,    g_ln2b);
    cudaGetSymbolAddress((void**)&p_hid,    g_hidb);
    cudaGetSymbolAddress((void**)&p_qkvwT,  g_qkvwT);
    cudaGetSymbolAddress((void**)&p_projwT, g_projwT);
    cudaGetSymbolAddress((void**)&p_w1T,    g_w1T);
    cudaGetSymbolAddress((void**)&p_w2T,    g_w2T);
    cudaGetSymbolAddress((void**)&p_bias,   g_bias);

    cudaFuncSetAttribute(tc_gemm<0,3,true>,  cudaFuncAttributeMaxDynamicSharedMemorySize, SM3);
    cudaFuncSetAttribute(tc_gemm<1,3,true>,  cudaFuncAttributeMaxDynamicSharedMemorySize, SM3);
    cudaFuncSetAttribute(tc_gemm<2,6,false>, cudaFuncAttributeMaxDynamicSharedMemorySize, SM6);
    cudaFuncSetAttribute(tc_gemm<3,3,false>, cudaFuncAttributeMaxDynamicSharedMemorySize, SM3);

    // 0. weight transposes + bias table
    transpose_all<<<dim3(24, 24, 4), dim3(32, 8)>>>(qkv_w, proj_w, w1, w2,
                                                    p_qkvwT, p_projwT, p_w1T, p_w2T);
    build_bias<<<24, 256>>>(rpb, p_bias);

    // 1. LN1 + shifted-window partition -> bf16
    ln_kernel<<<MROWS / 8, 256>>>(x, ln1_g, ln1_b, p_win);

    // 2. QKV: (100352,192) @ (192,576) -> bf16
    tc_gemm<0,3,true><<<dim3(MROWS / 128, 6), 256, SM3>>>(
        p_win, p_qkvwT, qkv_b, p_qkv, 576, 192, nullptr, nullptr, nullptr, nullptr);

    // 3. windowed attention (register flash; grid = window x head-pair)
    attn_kernel<<<dim3(NWIN, 3), 256>>>(p_bias);

    // 4. proj + window-reverse + residual(x) + fused LN2 (g_h fp32, g_ln2 bf16)
    tc_gemm<2,6,false><<<dim3(MROWS / 128, 1), 256, SM6>>>(
        p_attno, p_projwT, proj_b, p_h, 192, 192, x, p_ln2, ln2_g, ln2_b);

    // 5. MLP1 + GELU -> bf16
    tc_gemm<1,3,true><<<dim3(MROWS / 128, 8), 256, SM3>>>(
        p_ln2, p_w1T, b1, p_hid, HID, 192, nullptr, nullptr, nullptr, nullptr);

    // 6. MLP2 + residual(h) -> fp32 out
    tc_gemm<3,3,false><<<dim3(MROWS / 128, 2), 256, SM3>>>(
        p_hid, p_w2T, b2, out, 192, HID, p_h, nullptr, nullptr, nullptr);
}

// round 13
// speedup vs baseline: 1.0354x; 1.0081x over previous
#include <cuda_runtime.h>
#include <cuda_bf16.h>
#include <cstdint>

// ---------------------------------------------------------------------------
// SwinBlock: B=32, H=W=56, C=192, heads=6, head_dim=32, WS=7, SS=3, N=49
// bf16 mma.sync GEMMs (full-K single-stage for K=192) + register flash attn.
// ---------------------------------------------------------------------------

#define HW      56
#define Cdim    192
#define NHEADS  6
#define HDIM    32
#define WSZ     7
#define SSH     3
#define NTOK    49
#define NWIN    2048
#define MROWS   100352
#define HID     768
#define SCALE   0.17677669529663687f
#define SROW    72      // pipelined kernel smem row (64 data + 8 pad)
#define SROWF   200     // full-K kernel smem row (192 data + 8 pad)

typedef __nv_bfloat16 bf16;
typedef __nv_bfloat162 bf162;

// -------------------------- scratch (device globals) -----------------------
__device__ __align__(16) bf16  g_winb [(size_t)MROWS * Cdim];
__device__ __align__(16) bf16  g_qkvb [(size_t)MROWS * 3 * Cdim];
__device__ __align__(16) bf16  g_attnob[(size_t)MROWS * Cdim];
__device__ __align__(16) float g_h    [(size_t)MROWS * Cdim];
__device__ __align__(16) bf16  g_ln2b [(size_t)MROWS * Cdim];
__device__ __align__(16) bf16  g_hidb [(size_t)MROWS * HID];
__device__ __align__(16) bf16  g_qkvwT[576 * 192];
__device__ __align__(16) bf16  g_projwT[192 * 192];
__device__ __align__(16) bf16  g_w1T  [HID * 192];
__device__ __align__(16) bf16  g_w2T  [192 * HID];
__device__ __align__(16) float g_bias [24 * 64 * 64];   // [cls*6+head][r][c]

// ------------------------------ helpers ------------------------------------
__device__ __forceinline__ void cpasync16(bf16* dst, const bf16* src) {
    uint32_t d = (uint32_t)__cvta_generic_to_shared(dst);
    asm volatile("cp.async.cg.shared.global [%0], [%1], 16;" :: "r"(d), "l"(src));
}
#define CP_COMMIT() asm volatile("cp.async.commit_group;" ::: "memory")

__device__ __forceinline__ void mma_bf16(float* d, const uint32_t* a, const uint32_t* b) {
    asm volatile(
        "mma.sync.aligned.m16n8k16.row.col.f32.bf16.bf16.f32 "
        "{%0,%1,%2,%3}, {%4,%5,%6,%7}, {%8,%9}, {%0,%1,%2,%3};"
        : "+f"(d[0]), "+f"(d[1]), "+f"(d[2]), "+f"(d[3])
        : "r"(a[0]), "r"(a[1]), "r"(a[2]), "r"(a[3]), "r"(b[0]), "r"(b[1]));
}

__device__ __forceinline__ void ldsm_x4(uint32_t* r, uint32_t addr) {
    asm volatile("ldmatrix.sync.aligned.m8n8.x4.shared.b16 {%0,%1,%2,%3}, [%4];"
        : "=r"(r[0]), "=r"(r[1]), "=r"(r[2]), "=r"(r[3]) : "r"(addr));
}
__device__ __forceinline__ void ldsm_x2(uint32_t* r, uint32_t addr) {
    asm volatile("ldmatrix.sync.aligned.m8n8.x2.shared.b16 {%0,%1}, [%2];"
        : "=r"(r[0]), "=r"(r[1]) : "r"(addr));
}

__device__ __forceinline__ uint32_t pack_bf162(float lo, float hi) {
    bf162 t = __floats2bfloat162_rn(lo, hi);
    return *(uint32_t*)&t;
}

__device__ __forceinline__ int permrow(int rw) {
    int win = rw / NTOK, n = rw - win * NTOK;
    int b   = win >> 6, wi = win & 63;
    int wh  = wi >> 3,  ww = wi & 7;
    int i   = n / WSZ,  j  = n - i * WSZ;
    int hs  = wh * WSZ + i + SSH; if (hs >= HW) hs -= HW;
    int ws  = ww * WSZ + j + SSH; if (ws >= HW) ws -= HW;
    return b * (HW * HW) + hs * HW + ws;
}

// ------------------ combined rpb + shift-mask bias table -------------------
__global__ void build_bias(const float* __restrict__ rpb_table, float* __restrict__ bias) {
    int idx = blockIdx.x;
    int cls = idx / NHEADS, head = idx - cls * NHEADS;
    int whE = cls >> 1, wwE = cls & 1;
    for (int e = threadIdx.x; e < 4096; e += 256) {
        int r = e >> 6, c = e & 63;
        float v = -1e30f;
        if (r < NTOK && c < NTOK) {
            int ri = r / 7, ci = r - ri * 7;
            int rj = c / 7, cj = c - rj * 7;
            v = rpb_table[((ri - rj + 6) * 13 + (ci - cj + 6)) * NHEADS + head];
            int gr = (whE ? (ri < 4 ? 1 : 2) : 0) * 3 + (wwE ? (ci < 4 ? 1 : 2) : 0);
            int gc = (whE ? (rj < 4 ? 1 : 2) : 0) * 3 + (wwE ? (cj < 4 ? 1 : 2) : 0);
            if (gr != gc) v -= 100.f;
        }
        bias[(size_t)idx * 4096 + e] = v;
    }
}

// ------------------ merged weight transpose (fp32 -> bf16 T) ----------------
__global__ void transpose_all(const float* __restrict__ qkvw,
                              const float* __restrict__ projw,
                              const float* __restrict__ w1,
                              const float* __restrict__ w2,
                              bf16* __restrict__ o0, bf16* __restrict__ o1,
                              bf16* __restrict__ o2, bf16* __restrict__ o3) {
    __shared__ float t[32][33];
    const float* in; bf16* out; int R, C;
    switch (blockIdx.z) {
        case 0: in = qkvw;  out = o0; R = 192; C = 576; break;
        case 1: in = projw; out = o1; R = 192; C = 192; break;
        case 2: in = w1;    out = o2; R = 192; C = 768; break;
        default:in = w2;    out = o3; R = 768; C = 192; break;
    }
    int bx = blockIdx.x * 32, by = blockIdx.y * 32;
    if (bx >= C || by >= R) return;
    int x = threadIdx.x, y0 = threadIdx.y;
    #pragma unroll
    for (int j = 0; j < 32; j += 8)
        t[y0 + j][x] = in[(size_t)(by + y0 + j) * C + bx + x];
    __syncthreads();
    #pragma unroll
    for (int j = 0; j < 32; j += 8)
        out[(size_t)(bx + y0 + j) * R + by + x] = __float2bfloat16_rn(t[x][y0 + j]);
}

// ------------------------- LN1 (warp/row, permuted read) -------------------
__global__ __launch_bounds__(256)
void ln_kernel(const float* __restrict__ in, const float* __restrict__ gamma,
               const float* __restrict__ beta, bf16* __restrict__ out) {
    int wid = threadIdx.x >> 5, lane = threadIdx.x & 31;
    int row = blockIdx.x * 8 + wid;
    int src = permrow(row);
    const float* p = in + (size_t)src * Cdim;

    float v[6];
    #pragma unroll
    for (int j = 0; j < 3; j++) {
        float2 xv = *(const float2*)&p[2 * lane + 64 * j];
        v[2 * j] = xv.x; v[2 * j + 1] = xv.y;
    }
    float s = v[0] + v[1] + v[2] + v[3] + v[4] + v[5];
    #pragma unroll
    for (int o = 16; o; o >>= 1) s += __shfl_xor_sync(0xffffffffu, s, o);
    float mu = s * (1.0f / Cdim);
    float sq = 0.f;
    #pragma unroll
    for (int j = 0; j < 6; j++) { v[j] -= mu; sq += v[j] * v[j]; }
    #pragma unroll
    for (int o = 16; o; o >>= 1) sq += __shfl_xor_sync(0xffffffffu, sq, o);
    float inv = rsqrtf(sq * (1.0f / Cdim) + 1e-5f);

    bf16* q = out + (size_t)row * Cdim;
    #pragma unroll
    for (int j = 0; j < 3; j++) {
        int c = 2 * lane + 64 * j;
        float o0 = v[2 * j] * inv * gamma[c] + beta[c];
        float o1 = v[2 * j + 1] * inv * gamma[c + 1] + beta[c + 1];
        *(bf162*)(q + c) = __floats2bfloat162_rn(o0, o1);
    }
}

// ----------------- full-K single-stage GEMM (K=192, CTA 128x96) ------------
// EPI: 0 plain, 1 GELU. Output bf16.
template<int EPI>
__global__ __launch_bounds__(256, 2)
void tc_gemm_fk(const bf16* __restrict__ A, const bf16* __restrict__ BT,
                const float* __restrict__ bias, bf16* __restrict__ C, int N) {
    extern __shared__ __align__(16) bf16 sm[];
    bf16* As = sm;                       // [128][SROWF]
    bf16* Bs = sm + 128 * SROWF;         // [96][SROWF]

    int tid  = threadIdx.x;
    int wid  = tid >> 5, lane = tid & 31;
    int g    = lane >> 2, tig = lane & 3;
    int wm   = wid & 1, wn = wid >> 1;
    int mBase = blockIdx.x * 128;
    int nBase = blockIdx.y * 96;

    // load full tiles: A 128x192 (3072 chunks), B 96x192 (2304 chunks)
    #pragma unroll
    for (int i = 0; i < 12; i++) {
        int idx = tid + i * 256;
        int r = idx / 24, ch = idx - r * 24;
        cpasync16(As + r * SROWF + ch * 8, A + (size_t)(mBase + r) * 192 + ch * 8);
    }
    #pragma unroll
    for (int i = 0; i < 9; i++) {
        int idx = tid + i * 256;
        int r = idx / 24, ch = idx - r * 24;
        cpasync16(Bs + r * SROWF + ch * 8, BT + (size_t)(nBase + r) * 192 + ch * 8);
    }
    CP_COMMIT();

    uint32_t aq = (uint32_t)__cvta_generic_to_shared(
        As + (wm * 64 + (lane & 15)) * SROWF + ((lane >> 4) << 3));
    uint32_t bq = (uint32_t)__cvta_generic_to_shared(
        Bs + (wn * 24 + (lane & 7)) * SROWF + (((lane >> 3) & 1) << 3));

    float acc[4][3][4];
    #pragma unroll
    for (int mt = 0; mt < 4; mt++)
        #pragma unroll
        for (int nt = 0; nt < 3; nt++)
            #pragma unroll
            for (int e = 0; e < 4; e++) acc[mt][nt][e] = 0.f;

    asm volatile("cp.async.wait_group 0;" ::: "memory");
    __syncthreads();

    #pragma unroll
    for (int s = 0; s < 12; s++) {
        uint32_t a[4][4], b[3][2];
        #pragma unroll
        for (int mt = 0; mt < 4; mt++)
            ldsm_x4(a[mt], aq + (mt * 16 * SROWF + s * 16) * 2);
        #pragma unroll
        for (int nt = 0; nt < 3; nt++)
            ldsm_x2(b[nt], bq + (nt * 8 * SROWF + s * 16) * 2);
        #pragma unroll
        for (int mt = 0; mt < 4; mt++)
            #pragma unroll
            for (int nt = 0; nt < 3; nt++)
                mma_bf16(acc[mt][nt], a[mt], b[nt]);
    }

    // epilogue
    #pragma unroll
    for (int mt = 0; mt < 4; mt++) {
        int r0 = mBase + wm * 64 + mt * 16 + g;
        int r1 = r0 + 8;
        #pragma unroll
        for (int nt = 0; nt < 3; nt++) {
            int c = nBase + wn * 24 + nt * 8 + 2 * tig;
            float2 bv = *(const float2*)(bias + c);
            float v0 = acc[mt][nt][0] + bv.x;
            float v1 = acc[mt][nt][1] + bv.y;
            float v2 = acc[mt][nt][2] + bv.x;
            float v3 = acc[mt][nt][3] + bv.y;
            if (EPI == 1) {
                v0 = 0.5f * v0 * (1.0f + erff(v0 * 0.70710678118654752f));
                v1 = 0.5f * v1 * (1.0f + erff(v1 * 0.70710678118654752f));
                v2 = 0.5f * v2 * (1.0f + erff(v2 * 0.70710678118654752f));
                v3 = 0.5f * v3 * (1.0f + erff(v3 * 0.70710678118654752f));
            }
            *(bf162*)(C + (size_t)r0 * N + c) = __floats2bfloat162_rn(v0, v1);
            *(bf162*)(C + (size_t)r1 * N + c) = __floats2bfloat162_rn(v2, v3);
        }
    }
}

// --------------------- pipelined GEMM (proj / mlp2) ------------------------
template<int CTA_N>
__device__ __forceinline__ void gload(const bf16* __restrict__ A,
                                      const bf16* __restrict__ BT,
                                      bf16* As, bf16* Bs,
                                      int mBase, int nBase, int K, int k0, int tid) {
    #pragma unroll
    for (int i = 0; i < 4; i++) {
        int idx = tid + i * 256;
        int r = idx >> 3, ch = idx & 7;
        cpasync16(As + r * SROW + ch * 8, A + (size_t)(mBase + r) * K + k0 + ch * 8);
    }
    #pragma unroll
    for (int i = 0; i < CTA_N * 8; i += 256) {
        int idx = tid + i;
        int r = idx >> 3, ch = idx & 7;
        cpasync16(Bs + r * SROW + ch * 8, BT + (size_t)(nBase + r) * K + k0 + ch * 8);
    }
    CP_COMMIT();
}

template<int EPI, int NT, bool OBF16>
__global__ __launch_bounds__(256, (NT == 3) ? 3 : 1)
void tc_gemm(const bf16* __restrict__ A, const bf16* __restrict__ BT,
             const float* __restrict__ bias, void* __restrict__ Cv,
             int N, int K, const float* __restrict__ resid,
             bf16* __restrict__ C2, const float* __restrict__ g2,
             const float* __restrict__ b2v) {
    constexpr int CTA_N = NT * 32;
    extern __shared__ __align__(16) bf16 sm[];
    bf16* AsBase = sm;
    bf16* BsBase = sm + 2 * 128 * SROW;

    int tid  = threadIdx.x;
    int wid  = tid >> 5, lane = tid & 31;
    int g    = lane >> 2, tig = lane & 3;
    int wm   = wid & 1, wn = wid >> 1;
    int mBase = blockIdx.x * 128;
    int nBase = blockIdx.y * CTA_N;
    int nk = K >> 6;

    int aRow = wm * 64 + (lane & 15);
    int aCol = (lane >> 4) << 3;
    int bRow = wn * NT * 8 + (lane & 7);
    int bCol = ((lane >> 3) & 1) << 3;

    float acc[4][NT][4];
    #pragma unroll
    for (int mt = 0; mt < 4; mt++)
        #pragma unroll
        for (int nt = 0; nt < NT; nt++)
            #pragma unroll
            for (int e = 0; e < 4; e++) acc[mt][nt][e] = 0.f;

    gload<CTA_N>(A, BT, AsBase, BsBase, mBase, nBase, K, 0, tid);

    for (int kt = 0; kt < nk; kt++) {
        int buf = kt & 1;
        if (kt + 1 < nk) {
            gload<CTA_N>(A, BT, AsBase + (buf ^ 1) * 128 * SROW,
                         BsBase + (buf ^ 1) * CTA_N * SROW,
                         mBase, nBase, K, (kt + 1) << 6, tid);
            asm volatile("cp.async.wait_group 1;" ::: "memory");
        } else {
            asm volatile("cp.async.wait_group 0;" ::: "memory");
        }
        __syncthreads();

        const bf16* As = AsBase + buf * 128 * SROW;
        const bf16* Bs = BsBase + buf * CTA_N * SROW;
        uint32_t aq = (uint32_t)__cvta_generic_to_shared(As + aRow * SROW + aCol);
        uint32_t bq = (uint32_t)__cvta_generic_to_shared(Bs + bRow * SROW + bCol);

        #pragma unroll
        for (int s = 0; s < 4; s++) {
            uint32_t a[4][4], b[NT][2];
            #pragma unroll
            for (int mt = 0; mt < 4; mt++)
                ldsm_x4(a[mt], aq + (mt * 16 * SROW + s * 16) * 2);
            #pragma unroll
            for (int nt = 0; nt < NT; nt++)
                ldsm_x2(b[nt], bq + (nt * 8 * SROW + s * 16) * 2);
            #pragma unroll
            for (int mt = 0; mt < 4; mt++)
                #pragma unroll
                for (int nt = 0; nt < NT; nt++)
                    mma_bf16(acc[mt][nt], a[mt], b[nt]);
        }
        __syncthreads();
    }

    // ---------------- epilogue ----------------
    float* s_sum = (float*)(sm + 2 * (128 + CTA_N) * SROW);
    float* s_sq  = s_sum + 512;

    #pragma unroll
    for (int mt = 0; mt < 4; mt++) {
        int lr0 = wm * 64 + mt * 16 + g;
        int lr1 = lr0 + 8;
        int r0 = mBase + lr0, r1 = mBase + lr1;
        int p0 = r0, p1 = r1;
        if (EPI == 2) { p0 = permrow(r0); p1 = permrow(r1); }

        float s0 = 0.f, q0 = 0.f, s1 = 0.f, q1 = 0.f;
        #pragma unroll
        for (int nt = 0; nt < NT; nt++) {
            int c = nBase + wn * NT * 8 + nt * 8 + 2 * tig;
            float2 bv = *(const float2*)(bias + c);
            float v0 = acc[mt][nt][0] + bv.x;
            float v1 = acc[mt][nt][1] + bv.y;
            float v2 = acc[mt][nt][2] + bv.x;
            float v3 = acc[mt][nt][3] + bv.y;
            if (EPI == 1) {
                v0 = 0.5f * v0 * (1.0f + erff(v0 * 0.70710678118654752f));
                v1 = 0.5f * v1 * (1.0f + erff(v1 * 0.70710678118654752f));
                v2 = 0.5f * v2 * (1.0f + erff(v2 * 0.70710678118654752f));
                v3 = 0.5f * v3 * (1.0f + erff(v3 * 0.70710678118654752f));
            } else if (EPI == 2) {
                float2 ra = *(const float2*)(resid + (size_t)p0 * Cdim + c);
                float2 rb = *(const float2*)(resid + (size_t)p1 * Cdim + c);
                v0 += ra.x; v1 += ra.y; v2 += rb.x; v3 += rb.y;
                s0 += v0 + v1; q0 += v0 * v0 + v1 * v1;
                s1 += v2 + v3; q1 += v2 * v2 + v3 * v3;
                acc[mt][nt][0] = v0; acc[mt][nt][1] = v1;
                acc[mt][nt][2] = v2; acc[mt][nt][3] = v3;
            } else if (EPI == 3) {
                float2 ra = *(const float2*)(resid + (size_t)r0 * Cdim + c);
                float2 rb = *(const float2*)(resid + (size_t)r1 * Cdim + c);
                v0 += ra.x; v1 += ra.y; v2 += rb.x; v3 += rb.y;
            }
            if (OBF16) {
                bf16* Cb = (bf16*)Cv;
                *(bf162*)(Cb + (size_t)p0 * N + c) = __floats2bfloat162_rn(v0, v1);
                *(bf162*)(Cb + (size_t)p1 * N + c) = __floats2bfloat162_rn(v2, v3);
            } else {
                float* Cf = (float*)Cv;
                *(float2*)(Cf + (size_t)p0 * N + c) = make_float2(v0, v1);
                *(float2*)(Cf + (size_t)p1 * N + c) = make_float2(v2, v3);
            }
        }
        if (EPI == 2) {
            #pragma unroll
            for (int o = 1; o < 4; o <<= 1) {
                s0 += __shfl_xor_sync(0xffffffffu, s0, o);
                q0 += __shfl_xor_sync(0xffffffffu, q0, o);
                s1 += __shfl_xor_sync(0xffffffffu, s1, o);
                q1 += __shfl_xor_sync(0xffffffffu, q1, o);
            }
            if (tig == 0) {
                s_sum[wn * 128 + lr0] = s0;  s_sq[wn * 128 + lr0] = q0;
                s_sum[wn * 128 + lr1] = s1;  s_sq[wn * 128 + lr1] = q1;
            }
        }
    }

    if (EPI == 2) {
        __syncthreads();
        #pragma unroll
        for (int mt = 0; mt < 4; mt++) {
            int lr0 = wm * 64 + mt * 16 + g;
            int lr1 = lr0 + 8;
            int p0 = permrow(mBase + lr0), p1 = permrow(mBase + lr1);
            float su0 = s_sum[lr0] + s_sum[128 + lr0] + s_sum[256 + lr0] + s_sum[384 + lr0];
            float sq0 = s_sq[lr0]  + s_sq[128 + lr0]  + s_sq[256 + lr0]  + s_sq[384 + lr0];
            float su1 = s_sum[lr1] + s_sum[128 + lr1] + s_sum[256 + lr1] + s_sum[384 + lr1];
            float sq1 = s_sq[lr1]  + s_sq[128 + lr1]  + s_sq[256 + lr1]  + s_sq[384 + lr1];
            float mu0 = su0 * (1.0f / Cdim);
            float mu1 = su1 * (1.0f / Cdim);
            float iv0 = rsqrtf(sq0 * (1.0f / Cdim) - mu0 * mu0 + 1e-5f);
            float iv1 = rsqrtf(sq1 * (1.0f / Cdim) - mu1 * mu1 + 1e-5f);
            #pragma unroll
            for (int nt = 0; nt < NT; nt++) {
                int c = wn * NT * 8 + nt * 8 + 2 * tig;
                float2 gv = *(const float2*)(g2 + c);
                float2 bb = *(const float2*)(b2v + c);
                float o0 = (acc[mt][nt][0] - mu0) * iv0 * gv.x + bb.x;
                float o1 = (acc[mt][nt][1] - mu0) * iv0 * gv.y + bb.y;
                float o2 = (acc[mt][nt][2] - mu1) * iv1 * gv.x + bb.x;
                float o3 = (acc[mt][nt][3] - mu1) * iv1 * gv.y + bb.y;
                *(bf162*)(C2 + (size_t)p0 * Cdim + c) = __floats2bfloat162_rn(o0, o1);
                *(bf162*)(C2 + (size_t)p1 * Cdim + c) = __floats2bfloat162_rn(o2, o3);
            }
        }
    }
}

// ------------------- register-resident flash attention ---------------------
__global__ __launch_bounds__(256)
void attn_kernel(const float* __restrict__ biasTab) {
    __shared__ __align__(16) bf16 Qs[2][64][40];
    __shared__ __align__(16) bf16 Ks[2][64][40];
    __shared__ __align__(16) bf16 Vt[2][32][72];   // [head][d][token]

    int win = blockIdx.x;
    int h0  = blockIdx.y * 2;
    int tid = threadIdx.x;
    int wid = tid >> 5, lane = tid & 31;
    int g = lane >> 2, tig = lane & 3;
    int hsel = wid >> 2, wm2 = wid & 3;
    int wi = win & 63;
    int wh = wi >> 3, ww = wi & 7;
    int cls = ((wh == 7) ? 2 : 0) + ((ww == 7) ? 1 : 0);

    for (int idx = tid; idx < 2 * 15 * 20; idx += 256) {
        int hh = idx / 300, rem = idx - hh * 300;
        int rr = 49 + rem / 20, e = rem % 20;
        *(uint32_t*)&Ks[hh][rr][e * 2] = 0u;
    }
    for (int idx = tid; idx < 2 * 32 * 15; idx += 256) {
        int hh = idx / 480, rem = idx - hh * 480;
        int d = rem / 15, n = 49 + rem % 15;
        Vt[hh][d][n] = __float2bfloat16(0.f);
    }

    const bf16* base = g_qkvb + (size_t)win * NTOK * 576;

    for (int idx = tid; idx < 784; idx += 256) {
        int n = idx >> 4, sub = idx & 15;
        int hh = sub >> 3, mat = (sub >> 2) & 1, ch = sub & 3;
        uint4 v = *(const uint4*)(base + (size_t)n * 576 + mat * 192 + (h0 + hh) * 32 + ch * 8);
        *(uint4*)(&(mat ? Ks : Qs)[hh][n][ch * 8]) = v;
    }
    for (int idx = tid; idx < 392; idx += 256) {
        int n = idx >> 3, hh = (idx >> 2) & 1, ch = idx & 3;
        uint4 v = *(const uint4*)(base + (size_t)n * 576 + 384 + (h0 + hh) * 32 + ch * 8);
        bf16 tmp[8]; *(uint4*)tmp = v;
        #pragma unroll
        for (int e = 0; e < 8; e++) Vt[hh][ch * 8 + e][n] = tmp[e];
    }
    __syncthreads();

    int r0 = wm2 * 16 + g, r1 = r0 + 8;
    float sf[8][4];
    #pragma unroll
    for (int j = 0; j < 8; j++)
        #pragma unroll
        for (int e = 0; e < 4; e++) sf[j][e] = 0.f;

    uint32_t q_addr = (uint32_t)__cvta_generic_to_shared(
        &Qs[hsel][wm2 * 16 + (lane & 15)][(lane >> 4) * 8]);
    uint32_t k_addr = (uint32_t)__cvta_generic_to_shared(
        &Ks[hsel][(lane & 7) + ((lane >> 3) & 1) * 8][(lane >> 4) * 8]);

    #pragma unroll
    for (int s = 0; s < 2; s++) {
        uint32_t a[4];
        ldsm_x4(a, q_addr + s * 32);
        #pragma unroll
        for (int jp = 0; jp < 4; jp++) {
            uint32_t bb[4];
            ldsm_x4(bb, k_addr + (jp * 16 * 40 + s * 16) * 2);
            uint32_t bA[2] = {bb[0], bb[2]};
            uint32_t bB[2] = {bb[1], bb[3]};
            mma_bf16(sf[2 * jp],     a, bA);
            mma_bf16(sf[2 * jp + 1], a, bB);
        }
    }

    const float* bp = biasTab + (size_t)(cls * NHEADS + h0 + hsel) * 4096;
    #pragma unroll
    for (int j = 0; j < 8; j++) {
        int c0 = j * 8 + 2 * tig;
        float2 ba = *(const float2*)(bp + r0 * 64 + c0);
        float2 bc = *(const float2*)(bp + r1 * 64 + c0);
        sf[j][0] = sf[j][0] * SCALE + ba.x;
        sf[j][1] = sf[j][1] * SCALE + ba.y;
        sf[j][2] = sf[j][2] * SCALE + bc.x;
        sf[j][3] = sf[j][3] * SCALE + bc.y;
    }

    float m0 = -1e30f, m1 = -1e30f;
    #pragma unroll
    for (int j = 0; j < 8; j++) {
        m0 = fmaxf(m0, fmaxf(sf[j][0], sf[j][1]));
        m1 = fmaxf(m1, fmaxf(sf[j][2], sf[j][3]));
    }
    m0 = fmaxf(m0, __shfl_xor_sync(0xffffffffu, m0, 1));
    m0 = fmaxf(m0, __shfl_xor_sync(0xffffffffu, m0, 2));
    m1 = fmaxf(m1, __shfl_xor_sync(0xffffffffu, m1, 1));
    m1 = fmaxf(m1, __shfl_xor_sync(0xffffffffu, m1, 2));
    float s0 = 0.f, s1 = 0.f;
    #pragma unroll
    for (int j = 0; j < 8; j++) {
        sf[j][0] = __expf(sf[j][0] - m0); s0 += sf[j][0];
        sf[j][1] = __expf(sf[j][1] - m0); s0 += sf[j][1];
        sf[j][2] = __expf(sf[j][2] - m1); s1 += sf[j][2];
        sf[j][3] = __expf(sf[j][3] - m1); s1 += sf[j][3];
    }
    s0 += __shfl_xor_sync(0xffffffffu, s0, 1);
    s0 += __shfl_xor_sync(0xffffffffu, s0, 2);
    s1 += __shfl_xor_sync(0xffffffffu, s1, 1);
    s1 += __shfl_xor_sync(0xffffffffu, s1, 2);
    float inv0 = __fdividef(1.0f, s0);
    float inv1 = __fdividef(1.0f, s1);

    uint32_t pa[4][4];
    #pragma unroll
    for (int ks = 0; ks < 4; ks++) {
        pa[ks][0] = pack_bf162(sf[2 * ks][0] * inv0, sf[2 * ks][1] * inv0);
        pa[ks][1] = pack_bf162(sf[2 * ks][2] * inv1, sf[2 * ks][3] * inv1);
        pa[ks][2] = pack_bf162(sf[2 * ks + 1][0] * inv0, sf[2 * ks + 1][1] * inv0);
        pa[ks][3] = pack_bf162(sf[2 * ks + 1][2] * inv1, sf[2 * ks + 1][3] * inv1);
    }

    uint32_t v_addr = (uint32_t)__cvta_generic_to_shared(
        &Vt[hsel][(lane & 7) + ((lane >> 3) & 1) * 8][(lane >> 4) * 8]);
    float of[4][4];
    #pragma unroll
    for (int t = 0; t < 4; t++)
        #pragma unroll
        for (int e = 0; e < 4; e++) of[t][e] = 0.f;
    #pragma unroll
    for (int ks = 0; ks < 4; ks++) {
        #pragma unroll
        for (int tp = 0; tp < 2; tp++) {
            uint32_t bb[4];
            ldsm_x4(bb, v_addr + (tp * 16 * 72 + ks * 16) * 2);
            uint32_t bA[2] = {bb[0], bb[2]};
            uint32_t bB[2] = {bb[1], bb[3]};
            mma_bf16(of[2 * tp],     pa[ks], bA);
            mma_bf16(of[2 * tp + 1], pa[ks], bB);
        }
    }

    int h = h0 + hsel;
    #pragma unroll
    for (int t = 0; t < 4; t++) {
        int c = t * 8 + 2 * tig;
        if (r0 < 49) {
            bf16* o = g_attnob + (size_t)(win * NTOK + r0) * Cdim + h * HDIM + c;
            *(bf162*)o = __floats2bfloat162_rn(of[t][0], of[t][1]);
        }
        if (r1 < 49) {
            bf16* o = g_attnob + (size_t)(win * NTOK + r1) * Cdim + h * HDIM + c;
            *(bf162*)o = __floats2bfloat162_rn(of[t][2], of[t][3]);
        }
    }
}

// ------------------------------ launcher -----------------------------------
#define SMFK ((128 + 96) * SROWF * 2)                      // 89600 B
#define SM3  (2 * (128 + 96) * SROW * 2)                   // 64512 B
#define SM6  (2 * (128 + 192) * SROW * 2 + 4096)           // 96256 B

extern "C" void kernel_launch(void* const* d_in, const int* in_sizes, int n_in,
                              void* d_out, int out_size) {
    const float* x      = (const float*)d_in[0];
    const float* qkv_w  = (const float*)d_in[1];
    const float* qkv_b  = (const float*)d_in[2];
    const float* proj_w = (const float*)d_in[3];
    const float* proj_b = (const float*)d_in[4];
    const float* rpb    = (const float*)d_in[5];
    const float* ln1_g  = (const float*)d_in[6];
    const float* ln1_b  = (const float*)d_in[7];
    const float* ln2_g  = (const float*)d_in[8];
    const float* ln2_b  = (const float*)d_in[9];
    const float* w1     = (const float*)d_in[10];
    const float* b1     = (const float*)d_in[11];
    const float* w2     = (const float*)d_in[12];
    const float* b2     = (const float*)d_in[13];
    float* out = (float*)d_out;

    bf16 *p_win, *p_qkv, *p_attno, *p_ln2, *p_hid;
    bf16 *p_qkvwT, *p_projwT, *p_w1T, *p_w2T;
    float *p_h, *p_bias;
    cudaGetSymbolAddress((void**)&p_win,    g_winb);
    cudaGetSymbolAddress((void**)&p_qkv,    g_qkvb);
    cudaGetSymbolAddress((void**)&p_attno,  g_attnob);
    cudaGetSymbolAddress((void**)&p_h,      g_h);
    cudaGetSymbolAddress((void**)&p_ln2,    g_ln2b);
    cudaGetSymbolAddress((void**)&p_hid,    g_hidb);
    cudaGetSymbolAddress((void**)&p_qkvwT,  g_qkvwT);
    cudaGetSymbolAddress((void**)&p_projwT, g_projwT);
    cudaGetSymbolAddress((void**)&p_w1T,    g_w1T);
    cudaGetSymbolAddress((void**)&p_w2T,    g_w2T);
    cudaGetSymbolAddress((void**)&p_bias,   g_bias);

    cudaFuncSetAttribute(tc_gemm_fk<0>,      cudaFuncAttributeMaxDynamicSharedMemorySize, SMFK);
    cudaFuncSetAttribute(tc_gemm_fk<1>,      cudaFuncAttributeMaxDynamicSharedMemorySize, SMFK);
    cudaFuncSetAttribute(tc_gemm<2,6,false>, cudaFuncAttributeMaxDynamicSharedMemorySize, SM6);
    cudaFuncSetAttribute(tc_gemm<3,3,false>, cudaFuncAttributeMaxDynamicSharedMemorySize, SM3);

    // 0. weight transposes + bias table
    transpose_all<<<dim3(24, 24, 4), dim3(32, 8)>>>(qkv_w, proj_w, w1, w2,
                                                    p_qkvwT, p_projwT, p_w1T, p_w2T);
    build_bias<<<24, 256>>>(rpb, p_bias);

    // 1. LN1 + shifted-window partition -> bf16
    ln_kernel<<<MROWS / 8, 256>>>(x, ln1_g, ln1_b, p_win);

    // 2. QKV: (100352,192) @ (192,576) -> bf16  (full-K single stage)
    tc_gemm_fk<0><<<dim3(MROWS / 128, 6), 256, SMFK>>>(p_win, p_qkvwT, qkv_b, p_qkv, 576);

    // 3. windowed attention
    attn_kernel<<<dim3(NWIN, 3), 256>>>(p_bias);

    // 4. proj + window-reverse + residual(x) + fused LN2
    tc_gemm<2,6,false><<<dim3(MROWS / 128, 1), 256, SM6>>>(
        p_attno, p_projwT, proj_b, p_h, 192, 192, x, p_ln2, ln2_g, ln2_b);

    // 5. MLP1 + GELU -> bf16  (full-K single stage)
    tc_gemm_fk<1><<<dim3(MROWS / 128, 8), 256, SMFK>>>(p_ln2, p_w1T, b1, p_hid, HID);

    // 6. MLP2 + residual(h) -> fp32 out
    tc_gemm<3,3,false><<<dim3(MROWS / 128, 2), 256, SM3>>>(
        p_hid, p_w2T, b2, out, 192, HID, p_h, nullptr, nullptr, nullptr);
}